// round 13
// baseline (speedup 1.0000x reference)
#include <cuda_runtime.h>
#include <cuda_fp16.h>

// ROIPooler: multi-level FPN RoIAlign (torchvision, aligned=True)
// Inputs: x2 [2,256,200,304], x3 [2,256,100,152], x4 [2,256,50,76],
//         x5 [2,256,25,38], boxes [2,256,4]   Output: [512,256,7,7] f32
//
// MEGA-KERNEL: blocks [0, 20192) transpose all levels to channels-last fp16
// scratch (tiles ordered x5,x4,x3,x2 so small levels complete first); blocks
// [20192, 21216) are gather blocks that spin (acquire) on a per-level done
// counter and then run the proven 2-bins-per-warp channels-last gather.
// Ascending-bid dispatch guarantees forward progress. Counters zeroed by a
// tiny kernel before the mega-kernel each launch (graph-replay safe).

#define OUTSZ 7
#define SRATE 2
#define NSAMP 14
#define NPTS  196
#define NBINS 49
#define C_TOT 256
#define N_PER_B 256
#define NBOX_TOT 512

#define HW0 (200*304)   // x2: 60800
#define HW1 (100*152)   // x3: 15200
#define HW2 (50*76)     // x4: 3800
#define HW3 (25*38)     // x5: 950
#define PX0 0
#define PX1 (2*HW0)
#define PX2 (PX1 + 2*HW1)
#define PX3 (PX2 + 2*HW2)
#define TOTAL_PX (PX3 + 2*HW3)  // 161500

// tiles (32 hw-positions each), ordered SMALL level first: x5,x4,x3,x2
#define T3 ((HW3 + 31) / 32)    // 30
#define T2 ((HW2 + 31) / 32)    // 119
#define T1 ((HW1 + 31) / 32)    // 475
#define T0 ((HW0 + 31) / 32)    // 1900
#define CB3 0
#define CB2 (CB3 + T3)          // 30
#define CB1 (CB2 + T2)          // 149
#define CB0 (CB1 + T1)          // 624
#define TILES_TOT (CB0 + T0)    // 2524

#define TB_TOTAL (TILES_TOT * 8)        // 20192 transpose blocks
#define GB_TOTAL (NBOX_TOT * 2)         // 1024 gather blocks
#define GRID_TOT (TB_TOTAL + GB_TOTAL)  // 21216

#define GTHREADS 256
#define C_PER 128

// 82.7 MB channels-last fp16 scratch (device global: allowed)
__device__ __align__(16) __half g_trans[(size_t)TOTAL_PX * C_TOT];
__device__ int g_done[4];   // per-level transpose-done counters (lvl0 = x2)

// done targets per gather-level index (0=x2,1=x3,2=x4,3=x5): tiles * 8
__constant__ int c_target[4] = { T0 * 8, T1 * 8, T2 * 8, T3 * 8 };

__device__ __forceinline__ int ld_acquire(const int* p)
{
    int v;
    asm volatile("ld.acquire.gpu.global.b32 %0, [%1];" : "=r"(v) : "l"(p));
    return v;
}

__global__ void zero_ctr_kernel()
{
    if (threadIdx.x < 4) g_done[threadIdx.x] = 0;
}

// shared-memory overlays
struct GSm {                       // gather: 31808 B
    int4   o4[NPTS];
    float4 w4[NPTS];
    float  out[C_PER * NBINS];
    int   y0[NSAMP], y1[NSAMP], x0[NSAMP], x1[NSAMP];
    float fy[NSAMP], fx[NSAMP], wy[NSAMP], wx[NSAMP];
};
struct TSm {                       // transpose: 8448 B
    float tile[64][33];
};

__global__ __launch_bounds__(GTHREADS)
void mega_kernel(const float* __restrict__ x2,
                 const float* __restrict__ x3,
                 const float* __restrict__ x4,
                 const float* __restrict__ x5,
                 const float* __restrict__ boxes,
                 float* __restrict__ out)
{
    __shared__ __align__(16) unsigned char s_raw[sizeof(GSm)];

    const int bid  = blockIdx.x;
    const int tid  = threadIdx.x;
    const int w    = tid >> 5;
    const int lane = tid & 31;

    if (bid < TB_TOTAL) {
        // ================= TRANSPOSE BLOCK =================
        TSm& S = *reinterpret_cast<TSm*>(s_raw);
        const int tileflat = bid >> 3;
        const int sub      = bid & 7;
        const int b        = sub >> 2;
        const int c0       = (sub & 3) * 64;

        const float* in;
        int HW, pxbase, tb, lvl;
        if (tileflat < CB2)      { in = x5; HW = HW3; pxbase = PX3; tb = CB3; lvl = 3; }
        else if (tileflat < CB1) { in = x4; HW = HW2; pxbase = PX2; tb = CB2; lvl = 2; }
        else if (tileflat < CB0) { in = x3; HW = HW1; pxbase = PX1; tb = CB1; lvl = 1; }
        else                     { in = x2; HW = HW0; pxbase = PX0; tb = CB0; lvl = 0; }

        const int hw0 = (tileflat - tb) * 32;
        const int hw  = hw0 + lane;
        if (hw < HW) {
            #pragma unroll
            for (int i = 0; i < 8; i++) {
                const int row = w * 8 + i;
                S.tile[row][lane] =
                    in[(size_t)(b * C_TOT + c0 + row) * HW + hw];
            }
        }
        __syncthreads();

        __half2* __restrict__ outp = (__half2*)g_trans;
        #pragma unroll
        for (int i = 0; i < 4; i++) {
            const int hwr = w * 4 + i;
            const int hww = hw0 + hwr;
            if (hww < HW) {
                const float a = S.tile[2 * lane    ][hwr];
                const float c = S.tile[2 * lane + 1][hwr];
                outp[(size_t)(pxbase + b * HW + hww) * (C_TOT / 2)
                     + (c0 >> 1) + lane] = __floats2half2_rn(a, c);
            }
        }
        // release: make writes visible, then signal
        __syncthreads();
        __threadfence();
        if (tid == 0) atomicAdd(&g_done[lvl], 1);
        return;
    }

    // ================= GATHER BLOCK =================
    GSm& S = *reinterpret_cast<GSm*>(s_raw);
    const int gbid = bid - TB_TOTAL;
    const int n    = gbid >> 1;
    const int cs   = gbid & 1;

    // ---- box params / level select (no scratch access yet) ----
    const float bx1 = __ldg(boxes + n * 4 + 0);
    const float by1 = __ldg(boxes + n * 4 + 1);
    const float bx2 = __ldg(boxes + n * 4 + 2);
    const float by2 = __ldg(boxes + n * 4 + 3);

    const float size = sqrtf((bx2 - bx1) * (by2 - by1));
    float lf = floorf(4.0f + log2f(size / 224.0f + 1e-8f));
    lf = fminf(fmaxf(lf, 2.0f), 5.0f);
    const int lvl = (int)lf - 2;
    const int b = n / N_PER_B;

    int H, W, HW, pxb;
    float scale;
    switch (lvl) {
        case 0:  H = 200; W = 304; HW = HW0; pxb = PX0; scale = 0.25f;    break;
        case 1:  H = 100; W = 152; HW = HW1; pxb = PX1; scale = 0.125f;   break;
        case 2:  H = 50;  W = 76;  HW = HW2; pxb = PX2; scale = 0.0625f;  break;
        default: H = 25;  W = 38;  HW = HW3; pxb = PX3; scale = 0.03125f; break;
    }
    const int pxbase = pxb + b * HW;

    const float X1 = bx1 * scale - 0.5f;
    const float Y1 = by1 * scale - 0.5f;
    const float bin_w = (bx2 - bx1) * scale / (float)OUTSZ;
    const float bin_h = (by2 - by1) * scale / (float)OUTSZ;

    // ---- stage 1: per-axis tables (independent of scratch) ----
    if (tid < NSAMP) {
        const int p = tid >> 1;
        const int s = tid & 1;
        const float g = (float)p + ((float)s + 0.5f) / (float)SRATE;
        {
            const float yc = Y1 + g * bin_h;
            const bool valid = (yc >= -1.0f) && (yc <= (float)H);
            float c = fminf(fmaxf(yc, 0.0f), (float)(H - 1));
            const float c0 = floorf(c);
            const int i0 = (int)c0;
            S.y0[tid] = i0;
            S.y1[tid] = min(i0 + 1, H - 1);
            S.fy[tid] = c - c0;
            S.wy[tid] = valid ? 1.0f : 0.0f;
        }
        {
            const float xc = X1 + g * bin_w;
            const bool valid = (xc >= -1.0f) && (xc <= (float)W);
            float c = fminf(fmaxf(xc, 0.0f), (float)(W - 1));
            const float c0 = floorf(c);
            const int i0 = (int)c0;
            S.x0[tid] = i0;
            S.x1[tid] = min(i0 + 1, W - 1);
            S.fx[tid] = c - c0;
            S.wx[tid] = valid ? 1.0f : 0.0f;
        }
    }
    __syncthreads();

    // ---- stage 2: per-sample-point corner offsets + weights ----
    for (int pt = tid; pt < NPTS; pt += GTHREADS) {
        const int iy = pt / NSAMP;
        const int ix = pt - iy * NSAMP;
        const float v   = S.wy[iy] * S.wx[ix] * 0.25f;
        const float fy  = S.fy[iy], ofy = 1.0f - fy;
        const float fx  = S.fx[ix], ofx = 1.0f - fx;
        const int r0 = S.y0[iy] * W;
        const int r1 = S.y1[iy] * W;
        const int c0 = S.x0[ix];
        const int c1 = S.x1[ix];
        S.o4[pt] = make_int4(r0 + c0, r0 + c1, r1 + c0, r1 + c1);
        S.w4[pt] = make_float4(v * ofy * ofx, v * ofy * fx,
                               v * fy  * ofx, v * fy  * fx);
    }

    // ---- wait for this level's transpose to finish (acquire) ----
    if (tid == 0) {
        const int target = c_target[lvl];
        while (ld_acquire(&g_done[lvl]) < target)
            __nanosleep(200);
    }
    __syncthreads();

    // ---- stage 3: channels-last gather, TWO bins per warp iteration ----
    const __half2* __restrict__ base =
        (const __half2*)g_trans + (size_t)pxbase * (C_TOT / 2) + cs * (C_PER / 2);

    for (int rA = w; rA < NBINS; rA += 16) {
        const int  rB   = rA + 8;
        const bool has2 = (rB < NBINS);

        const int phA = rA / OUTSZ, pwA = rA - phA * OUTSZ;
        const int ptA = (2 * phA) * NSAMP + 2 * pwA;
        const int rBs = has2 ? rB : rA;
        const int phB = rBs / OUTSZ, pwB = rBs - phB * OUTSZ;
        const int ptB = (2 * phB) * NSAMP + 2 * pwB;
        const float mB = has2 ? 1.0f : 0.0f;

        float A0 = 0.f, A1 = 0.f, A2 = 0.f, A3 = 0.f;
        float B0 = 0.f, B1 = 0.f, B2 = 0.f, B3 = 0.f;

        #pragma unroll
        for (int sy = 0; sy < SRATE; sy++) {
            #pragma unroll
            for (int sx = 0; sx < SRATE; sx++) {
                const int dpt = sy * NSAMP + sx;
                const int4   oA = S.o4[ptA + dpt];
                const float4 wA = S.w4[ptA + dpt];
                const int4   oB = S.o4[ptB + dpt];
                float4 wB = S.w4[ptB + dpt];
                wB.x *= mB; wB.y *= mB; wB.z *= mB; wB.w *= mB;

                #define CORNER(OFF, WT, P, Q, R, Ss)                           \
                {                                                              \
                    const uint2 raw =                                          \
                        ((const uint2*)(base + (size_t)(OFF) * (C_TOT / 2)))[lane]; \
                    const float2 f0 = __half22float2(*(const __half2*)&raw.x); \
                    const float2 f1 = __half22float2(*(const __half2*)&raw.y); \
                    P  = fmaf(f0.x, (WT), P);                                  \
                    Q  = fmaf(f0.y, (WT), Q);                                  \
                    R  = fmaf(f1.x, (WT), R);                                  \
                    Ss = fmaf(f1.y, (WT), Ss);                                 \
                }
                CORNER(oA.x, wA.x, A0, A1, A2, A3)
                CORNER(oA.y, wA.y, A0, A1, A2, A3)
                CORNER(oA.z, wA.z, A0, A1, A2, A3)
                CORNER(oA.w, wA.w, A0, A1, A2, A3)
                CORNER(oB.x, wB.x, B0, B1, B2, B3)
                CORNER(oB.y, wB.y, B0, B1, B2, B3)
                CORNER(oB.z, wB.z, B0, B1, B2, B3)
                CORNER(oB.w, wB.w, B0, B1, B2, B3)
                #undef CORNER
            }
        }

        const int cl = lane * 4;
        S.out[(cl + 0) * NBINS + rA] = A0;
        S.out[(cl + 1) * NBINS + rA] = A1;
        S.out[(cl + 2) * NBINS + rA] = A2;
        S.out[(cl + 3) * NBINS + rA] = A3;
        if (has2) {
            S.out[(cl + 0) * NBINS + rB] = B0;
            S.out[(cl + 1) * NBINS + rB] = B1;
            S.out[(cl + 2) * NBINS + rB] = B2;
            S.out[(cl + 3) * NBINS + rB] = B3;
        }
    }
    __syncthreads();

    // ---- flush: out slice for (box, cs) is linear 128*49 floats ----
    float4* __restrict__ oc =
        (float4*)(out + (size_t)n * (C_TOT * NBINS) + (size_t)cs * (C_PER * NBINS));
    const float4* __restrict__ so = (const float4*)S.out;
    for (int i = tid; i < (C_PER * NBINS) / 4; i += GTHREADS)
        oc[i] = so[i];
}

extern "C" void kernel_launch(void* const* d_in, const int* in_sizes, int n_in,
                              void* d_out, int out_size)
{
    const float* x2    = (const float*)d_in[0];
    const float* x3    = (const float*)d_in[1];
    const float* x4    = (const float*)d_in[2];
    const float* x5    = (const float*)d_in[3];
    const float* boxes = (const float*)d_in[4];
    float* out = (float*)d_out;

    zero_ctr_kernel<<<1, 32>>>();
    mega_kernel<<<GRID_TOT, GTHREADS>>>(x2, x3, x4, x5, boxes, out);
}

// round 14
// speedup vs baseline: 1.1270x; 1.1270x over previous
#include <cuda_runtime.h>
#include <cuda_fp16.h>

// ROIPooler: multi-level FPN RoIAlign (torchvision, aligned=True)
// Inputs: x2 [2,256,200,304], x3 [2,256,100,152], x4 [2,256,50,76],
//         x5 [2,256,25,38], boxes [2,256,4]   Output: [512,256,7,7] f32
//
// Phase 1 (4 launches, near bandwidth-bound): transpose each level to
//   channels-last fp16 scratch g_trans[(pxbase + b*HW + y*W + x)*256 + c].
// Phase 2: per (box, 128-ch) block. 2 bins per warp iteration. Per sample
//   point, the 4 bilinear corners are accumulated in half2 via HFMA2
//   (weights pre-packed as half2), converted ONCE per point to f32 and
//   folded into the bin accumulators — ~45% fewer hot-loop instructions
//   than per-corner f32 cvt+FMA. Staging/flush = proven R8/R12 layout.

#define OUTSZ 7
#define SRATE 2
#define NSAMP 14
#define NPTS  196
#define NBINS 49
#define C_TOT 256
#define N_PER_B 256
#define NBOX_TOT 512

#define HW0 (200*304)   // 60800
#define HW1 (100*152)   // 15200
#define HW2 (50*76)     // 3800
#define HW3 (25*38)     // 950
#define PX0 0
#define PX1 (2*HW0)
#define PX2 (PX1 + 2*HW1)
#define PX3 (PX2 + 2*HW2)
#define TOTAL_PX (PX3 + 2*HW3)  // 161500

// 82.7 MB channels-last fp16 scratch (device global: allowed)
__device__ __align__(16) __half g_trans[(size_t)TOTAL_PX * C_TOT];

// ---------------- phase 1: [B,C,HW] f32 -> [B,HW,C] fp16 -------------------
__global__ __launch_bounds__(256)
void transpose_kernel(const float* __restrict__ in, int HW, int pxbase)
{
    __shared__ float tile[64][33];
    const int hw0 = blockIdx.x * 32;
    const int c0  = blockIdx.y * 64;
    const int b   = blockIdx.z;
    const int w    = threadIdx.x >> 5;
    const int lane = threadIdx.x & 31;

    const int hw = hw0 + lane;
    if (hw < HW) {
        #pragma unroll
        for (int i = 0; i < 8; i++) {
            const int row = w * 8 + i;
            tile[row][lane] =
                in[(size_t)(b * C_TOT + c0 + row) * HW + hw];
        }
    }
    __syncthreads();

    __half2* __restrict__ outp = (__half2*)g_trans;
    #pragma unroll
    for (int i = 0; i < 4; i++) {
        const int hwr = w * 4 + i;
        const int hww = hw0 + hwr;
        if (hww < HW) {
            const float a = tile[2 * lane    ][hwr];
            const float c = tile[2 * lane + 1][hwr];
            outp[(size_t)(pxbase + b * HW + hww) * (C_TOT / 2)
                 + (c0 >> 1) + lane] = __floats2half2_rn(a, c);
        }
    }
}

// ---------------- phase 2: gather (HFMA2 point accumulation) ---------------
#define GTHREADS 256
#define CSPLIT 2
#define C_PER 128

__global__ __launch_bounds__(GTHREADS)
void gather_kernel(const float* __restrict__ boxes, float* __restrict__ out)
{
    __shared__ int   s_y0[NSAMP], s_y1[NSAMP], s_x0[NSAMP], s_x1[NSAMP];
    __shared__ float s_fy[NSAMP], s_fx[NSAMP], s_wy[NSAMP], s_wx[NSAMP];
    __shared__ __align__(16) int4  s_o4[NPTS];   // 4 corner pixel offsets
    __shared__ __align__(16) uint4 s_wh[NPTS];   // 4 half2-packed weights
    __shared__ __align__(16) float s_out[C_PER * NBINS];   // 25088 B

    const int n    = blockIdx.x;
    const int cs   = blockIdx.y;
    const int tid  = threadIdx.x;
    const int w    = tid >> 5;
    const int lane = tid & 31;

    // ---- box params / level select ----
    const float bx1 = __ldg(boxes + n * 4 + 0);
    const float by1 = __ldg(boxes + n * 4 + 1);
    const float bx2 = __ldg(boxes + n * 4 + 2);
    const float by2 = __ldg(boxes + n * 4 + 3);

    const float size = sqrtf((bx2 - bx1) * (by2 - by1));
    float lf = floorf(4.0f + log2f(size / 224.0f + 1e-8f));
    lf = fminf(fmaxf(lf, 2.0f), 5.0f);
    const int lvl = (int)lf - 2;
    const int b = n / N_PER_B;

    int H, W, HW, pxb;
    float scale;
    switch (lvl) {
        case 0:  H = 200; W = 304; HW = HW0; pxb = PX0; scale = 0.25f;    break;
        case 1:  H = 100; W = 152; HW = HW1; pxb = PX1; scale = 0.125f;   break;
        case 2:  H = 50;  W = 76;  HW = HW2; pxb = PX2; scale = 0.0625f;  break;
        default: H = 25;  W = 38;  HW = HW3; pxb = PX3; scale = 0.03125f; break;
    }
    const int pxbase = pxb + b * HW;

    const float X1 = bx1 * scale - 0.5f;
    const float Y1 = by1 * scale - 0.5f;
    const float bin_w = (bx2 - bx1) * scale / (float)OUTSZ;
    const float bin_h = (by2 - by1) * scale / (float)OUTSZ;

    // ---- stage 1: per-axis tables ----
    if (tid < NSAMP) {
        const int p = tid >> 1;
        const int s = tid & 1;
        const float g = (float)p + ((float)s + 0.5f) / (float)SRATE;
        {
            const float yc = Y1 + g * bin_h;
            const bool valid = (yc >= -1.0f) && (yc <= (float)H);
            float c = fminf(fmaxf(yc, 0.0f), (float)(H - 1));
            const float c0 = floorf(c);
            const int i0 = (int)c0;
            s_y0[tid] = i0;
            s_y1[tid] = min(i0 + 1, H - 1);
            s_fy[tid] = c - c0;
            s_wy[tid] = valid ? 1.0f : 0.0f;
        }
        {
            const float xc = X1 + g * bin_w;
            const bool valid = (xc >= -1.0f) && (xc <= (float)W);
            float c = fminf(fmaxf(xc, 0.0f), (float)(W - 1));
            const float c0 = floorf(c);
            const int i0 = (int)c0;
            s_x0[tid] = i0;
            s_x1[tid] = min(i0 + 1, W - 1);
            s_fx[tid] = c - c0;
            s_wx[tid] = valid ? 1.0f : 0.0f;
        }
    }
    __syncthreads();

    // ---- stage 2: per-point corner offsets + half2-packed weights ----
    for (int pt = tid; pt < NPTS; pt += GTHREADS) {
        const int iy = pt / NSAMP;
        const int ix = pt - iy * NSAMP;
        const float v   = s_wy[iy] * s_wx[ix] * 0.25f;
        const float fy  = s_fy[iy], ofy = 1.0f - fy;
        const float fx  = s_fx[ix], ofx = 1.0f - fx;
        const int r0 = s_y0[iy] * W;
        const int r1 = s_y1[iy] * W;
        const int c0 = s_x0[ix];
        const int c1 = s_x1[ix];
        s_o4[pt] = make_int4(r0 + c0, r0 + c1, r1 + c0, r1 + c1);
        const __half2 w00 = __float2half2_rn(v * ofy * ofx);
        const __half2 w01 = __float2half2_rn(v * ofy * fx);
        const __half2 w10 = __float2half2_rn(v * fy  * ofx);
        const __half2 w11 = __float2half2_rn(v * fy  * fx);
        uint4 packed;
        packed.x = *(const unsigned int*)&w00;
        packed.y = *(const unsigned int*)&w01;
        packed.z = *(const unsigned int*)&w10;
        packed.w = *(const unsigned int*)&w11;
        s_wh[pt] = packed;
    }
    __syncthreads();

    // ---- stage 3: channels-last gather, 2 bins/warp-iter, HFMA2 points ----
    const __half2* __restrict__ base =
        (const __half2*)g_trans + (size_t)pxbase * (C_TOT / 2) + cs * (C_PER / 2);

    for (int rA = w; rA < NBINS; rA += 16) {
        const int  rB   = rA + 8;
        const bool has2 = (rB < NBINS);

        const int phA = rA / OUTSZ, pwA = rA - phA * OUTSZ;
        const int ptA = (2 * phA) * NSAMP + 2 * pwA;
        const int rBs = has2 ? rB : rA;
        const int phB = rBs / OUTSZ, pwB = rBs - phB * OUTSZ;
        const int ptB = (2 * phB) * NSAMP + 2 * pwB;
        const float mB = has2 ? 1.0f : 0.0f;

        float A0 = 0.f, A1 = 0.f, A2 = 0.f, A3 = 0.f;
        float B0 = 0.f, B1 = 0.f, B2 = 0.f, B3 = 0.f;

        #pragma unroll
        for (int sy = 0; sy < SRATE; sy++) {
            #pragma unroll
            for (int sx = 0; sx < SRATE; sx++) {
                const int dpt = sy * NSAMP + sx;

                // ---- point for bin A: half2-accumulate 4 corners ----
                {
                    const int4  o  = s_o4[ptA + dpt];
                    const uint4 wh = s_wh[ptA + dpt];
                    __half2 acc0 = __float2half2_rn(0.f);
                    __half2 acc1 = __float2half2_rn(0.f);
                    #define PCORN(OFF, WRAW)                                   \
                    {                                                          \
                        const uint2 raw =                                      \
                            ((const uint2*)(base + (size_t)(OFF) * (C_TOT / 2)))[lane]; \
                        const __half2 w2 = *(const __half2*)&(WRAW);           \
                        acc0 = __hfma2(*(const __half2*)&raw.x, w2, acc0);     \
                        acc1 = __hfma2(*(const __half2*)&raw.y, w2, acc1);     \
                    }
                    PCORN(o.x, wh.x)
                    PCORN(o.y, wh.y)
                    PCORN(o.z, wh.z)
                    PCORN(o.w, wh.w)
                    const float2 f0 = __half22float2(acc0);
                    const float2 f1 = __half22float2(acc1);
                    A0 += f0.x; A1 += f0.y; A2 += f1.x; A3 += f1.y;
                }
                // ---- point for bin B ----
                {
                    const int4  o  = s_o4[ptB + dpt];
                    const uint4 wh = s_wh[ptB + dpt];
                    __half2 acc0 = __float2half2_rn(0.f);
                    __half2 acc1 = __float2half2_rn(0.f);
                    PCORN(o.x, wh.x)
                    PCORN(o.y, wh.y)
                    PCORN(o.z, wh.z)
                    PCORN(o.w, wh.w)
                    #undef PCORN
                    const float2 f0 = __half22float2(acc0);
                    const float2 f1 = __half22float2(acc1);
                    B0 += f0.x * mB; B1 += f0.y * mB;
                    B2 += f1.x * mB; B3 += f1.y * mB;
                }
            }
        }

        const int cl = lane * 4;
        s_out[(cl + 0) * NBINS + rA] = A0;
        s_out[(cl + 1) * NBINS + rA] = A1;
        s_out[(cl + 2) * NBINS + rA] = A2;
        s_out[(cl + 3) * NBINS + rA] = A3;
        if (has2) {
            s_out[(cl + 0) * NBINS + rB] = B0;
            s_out[(cl + 1) * NBINS + rB] = B1;
            s_out[(cl + 2) * NBINS + rB] = B2;
            s_out[(cl + 3) * NBINS + rB] = B3;
        }
    }
    __syncthreads();

    // ---- flush: out slice for (box, cs) is linear 128*49 floats ----
    float4* __restrict__ oc =
        (float4*)(out + (size_t)n * (C_TOT * NBINS) + (size_t)cs * (C_PER * NBINS));
    const float4* __restrict__ so = (const float4*)s_out;
    for (int i = tid; i < (C_PER * NBINS) / 4; i += GTHREADS)
        oc[i] = so[i];
}

extern "C" void kernel_launch(void* const* d_in, const int* in_sizes, int n_in,
                              void* d_out, int out_size)
{
    const float* x2    = (const float*)d_in[0];
    const float* x3    = (const float*)d_in[1];
    const float* x4    = (const float*)d_in[2];
    const float* x5    = (const float*)d_in[3];
    const float* boxes = (const float*)d_in[4];
    float* out = (float*)d_out;

    transpose_kernel<<<dim3((HW0 + 31) / 32, 4, 2), 256>>>(x2, HW0, PX0);
    transpose_kernel<<<dim3((HW1 + 31) / 32, 4, 2), 256>>>(x3, HW1, PX1);
    transpose_kernel<<<dim3((HW2 + 31) / 32, 4, 2), 256>>>(x4, HW2, PX2);
    transpose_kernel<<<dim3((HW3 + 31) / 32, 4, 2), 256>>>(x5, HW3, PX3);

    gather_kernel<<<dim3(NBOX_TOT, CSPLIT), GTHREADS>>>(boxes, out);
}